// round 5
// baseline (speedup 1.0000x reference)
#include <cuda_runtime.h>
#include <cstdint>

#define BATCH 4
#define SEQLEN 4096
#define DMODEL 1024
#define DSTATE 16
#define NROWS (BATCH*SEQLEN)
#define NCHUNK 128                // chunks per sequence; chunk = 32 timesteps

// Scratch in [b][s][n] layout (contiguous per sequence)
__device__ float g_bx[NROWS*DSTATE];
__device__ float g_decay[NROWS*DSTATE];
__device__ float g_cA[BATCH*DSTATE*NCHUNK];
__device__ float g_cH[BATCH*DSTATE*NCHUNK];
__device__ float g_hpre[BATCH*DSTATE*NCHUNK];

// ---- packed f32x2 helpers ---------------------------------------------------
__device__ __forceinline__ double pk2(float lo, float hi) {
    double d; asm("mov.b64 %0, {%1, %2};" : "=d"(d) : "f"(lo), "f"(hi)); return d;
}
__device__ __forceinline__ double fma2(double a, double b, double c) {
    double d; asm("fma.rn.f32x2 %0, %1, %2, %3;" : "=d"(d) : "d"(a), "d"(b), "d"(c)); return d;
}
__device__ __forceinline__ double mul2(double a, double b) {
    double d; asm("mul.rn.f32x2 %0, %1, %2;" : "=d"(d) : "d"(a), "d"(b)); return d;
}
__device__ __forceinline__ double add2(double a, double b) {
    double d; asm("add.rn.f32x2 %0, %1, %2;" : "=d"(d) : "d"(a), "d"(b)); return d;
}
__device__ __forceinline__ float lo2(double d) { return __int_as_float(__double2loint(d)); }
__device__ __forceinline__ float hi2(double d) { return __int_as_float(__double2hiint(d)); }

// ---------------------------------------------------------------------------
// Kernel 1: Bx = x @ B_in ; decay = exp(softplus(Bx) * -exp(A))
// 256 threads / 64 rows. Thread (c=t&15, rgrp=t>>4) owns 4 rows, e = c+16k.
// B tile XOR-swizzled in 16B units: logical unit u of row e lives at
// phys = 4e + (u ^ (e&3)). Per LDS.128, 16 unique lanes hit every 16B bank
// group exactly twice -> 2 phases / 256B = full crossbar BW.
// Emits per-32-row chunk affine summaries (2 per block).
// ---------------------------------------------------------------------------
__global__ __launch_bounds__(256, 3) void bx_kernel(const float* __restrict__ x,
                                                    const float* __restrict__ A,
                                                    const float* __restrict__ B_in) {
    __shared__ __align__(16) uint4 sb4[1024];      // 16 KB: 256 e x 4 units
    __shared__ double sdump[64][8];                // 4 KB
    __shared__ float sdec[DSTATE][65];
    __shared__ float sbxs[DSTATE][65];

    const int t = threadIdx.x;
    const int c = t & 15;
    const int rgrp = t >> 4;
    const int row0 = blockIdx.x * 64 + rgrp * 4;

    double acc[4][8];
#pragma unroll
    for (int r = 0; r < 4; r++)
#pragma unroll
        for (int j = 0; j < 8; j++) acc[r][j] = 0.0;

    for (int ch = 0; ch < 4; ch++) {
        __syncthreads();
        // stage 256 B-rows as swizzled 16B units (coalesced uint4 reads)
        const uint4* bsrc = (const uint4*)(B_in + (size_t)ch * 256 * DSTATE);
#pragma unroll
        for (int i = 0; i < 4; i++) {
            int idx = i * 256 + t;                 // unit index 0..1023
            int e = idx >> 2, u = idx & 3;
            sb4[(e << 2) | (u ^ (e & 3))] = bsrc[idx];
        }
        __syncthreads();

        const float* xp = x + (size_t)row0 * DMODEL + ch * 256 + c;
#pragma unroll
        for (int k = 0; k < 16; k++) {
            double xx[4];
#pragma unroll
            for (int r = 0; r < 4; r++) {
                const float xv = xp[r * DMODEL + k * 16];
                xx[r] = pk2(xv, xv);
            }
            const int e = c + 16 * k;
            const int base = e << 2, sw = e & 3;
#pragma unroll
            for (int up = 0; up < 2; up++) {
                const double2 b0 = *(const double2*)&sb4[base | ((2 * up) ^ sw)];
                const double2 b1 = *(const double2*)&sb4[base | ((2 * up + 1) ^ sw)];
#pragma unroll
                for (int r = 0; r < 4; r++) {
                    acc[r][4 * up + 0] = fma2(xx[r], b0.x, acc[r][4 * up + 0]);
                    acc[r][4 * up + 1] = fma2(xx[r], b0.y, acc[r][4 * up + 1]);
                    acc[r][4 * up + 2] = fma2(xx[r], b1.x, acc[r][4 * up + 2]);
                    acc[r][4 * up + 3] = fma2(xx[r], b1.y, acc[r][4 * up + 3]);
                }
            }
        }
    }

    // reduce across the 16 c-lanes
#pragma unroll
    for (int off = 1; off < 16; off <<= 1) {
#pragma unroll
        for (int r = 0; r < 4; r++)
#pragma unroll
            for (int j = 0; j < 8; j++) {
                double o = __shfl_xor_sync(0xffffffffu, acc[r][j], off);
                acc[r][j] = add2(acc[r][j], o);
            }
    }

    __syncthreads();
    if (c == 0) {
#pragma unroll
        for (int r = 0; r < 4; r++)
#pragma unroll
            for (int j = 0; j < 8; j++) sdump[rgrp * 4 + r][j] = acc[r][j];
    }
    __syncthreads();

    // softplus/exp: thread t -> row t>>2, s-quad t&3
    {
        const int rl = t >> 2, q = t & 3;
        const double v0 = sdump[rl][2 * q];
        const double v1 = sdump[rl][2 * q + 1];
        float bxv[4] = { lo2(v0), hi2(v0), lo2(v1), hi2(v1) };
#pragma unroll
        for (int j = 0; j < 4; j++) {
            const int s = 4 * q + j;
            const float an = -expf(A[s]);
            const float bx = bxv[j];
            const float sp = (bx > 20.f) ? bx : log1pf(expf(bx));
            sdec[s][rl] = expf(sp * an);
            sbxs[s][rl] = bx;
        }
    }
    __syncthreads();

    const int b = blockIdx.x >> 6;
    const int n0 = (blockIdx.x * 64) & (SEQLEN - 1);
#pragma unroll
    for (int i = 0; i < 4; i++) {
        int idx = i * 256 + t;
        int s = idx >> 6, j = idx & 63;
        size_t o = ((size_t)(b * DSTATE + s)) * SEQLEN + n0 + j;
        g_bx[o] = sbxs[s][j];
        g_decay[o] = sdec[s][j];
    }
    // per-32-row chunk summaries (two chunks per block), warp 0
    if (t < 32) {
        const int s = t & 15, half = t >> 4;
        float a = 1.f, h = 0.f;
#pragma unroll
        for (int j = 0; j < 32; j++) {
            const int jj = half * 32 + j;
            const float d = sdec[s][jj];
            h = fmaf(h, d, sbxs[s][jj]);
            a *= d;
        }
        const int so = (b * DSTATE + s) * NCHUNK + (n0 >> 5) + half;
        g_cA[so] = a;
        g_cH[so] = h;
    }
}

// ---------------------------------------------------------------------------
// Kernel 2: scan 128 chunk summaries per (b,s); write EXCLUSIVE prefix.
// ---------------------------------------------------------------------------
__global__ __launch_bounds__(128) void chunkscan_kernel() {
    __shared__ float sA[128], sH[128];
    const int t = threadIdx.x;
    const int seq = blockIdx.x;                    // b*16 + s
    float a = g_cA[seq * NCHUNK + t];
    float h = g_cH[seq * NCHUNK + t];
    sA[t] = a; sH[t] = h;
    __syncthreads();
#pragma unroll
    for (int off = 1; off < 128; off <<= 1) {
        float pa = 1.f, ph = 0.f;
        const bool act = (t >= off);
        if (act) { pa = sA[t - off]; ph = sH[t - off]; }
        __syncthreads();
        if (act) {
            h = fmaf(a, ph, h);
            a = a * pa;
            sA[t] = a; sH[t] = h;
        }
        __syncthreads();
    }
    g_hpre[seq * NCHUNK + t] = (t == 0) ? 0.f : sH[t - 1];
}

// ---------------------------------------------------------------------------
// Kernel 3: replay 32-row chunk from prefix + y = hs@C + x*D
// Block: 32 rows x 1024 cols, 256 threads; thread owns cols [4t,4t+4).
// x/y move as natural double2 (16B); C in natural packed doubles; h
// duplicated (h,h) in smem so the hot loop is LDS.64-broadcast + FFMA2 only.
// ---------------------------------------------------------------------------
__global__ __launch_bounds__(256) void out_kernel(const float* __restrict__ x,
                                                  const float* __restrict__ C,
                                                  const float* __restrict__ D,
                                                  float* __restrict__ y) {
    __shared__ float sd[DSTATE][33], sv[DSTATE][33];
    __shared__ __align__(8) double shh2[DSTATE][33];
    const int t = threadIdx.x;
    const int row0 = blockIdx.x * 32;
    const int b = row0 >> 12, n0 = row0 & (SEQLEN - 1);
    const int chunk = n0 >> 5;

    // stage decay/bx tiles [16 s][32 n] (coalesced)
#pragma unroll
    for (int i = 0; i < 2; i++) {
        int idx = i * 256 + t;
        int s = idx >> 5, j = idx & 31;
        size_t o = ((size_t)(b * DSTATE + s)) * SEQLEN + n0 + j;
        sd[s][j] = g_decay[o];
        sv[s][j] = g_bx[o];
    }
    __syncthreads();

    // replay recurrence for this chunk; store h duplicated as (h,h)
    if (t < DSTATE) {
        float h = g_hpre[(b * DSTATE + t) * NCHUNK + chunk];
#pragma unroll
        for (int j = 0; j < 32; j++) {
            h = fmaf(h, sd[t][j], sv[t][j]);
            shh2[t][j] = pk2(h, h);
        }
    }
    __syncthreads();

    // C columns [4t, 4t+4) as natural packed doubles
    double cd0[16], cd1[16];
#pragma unroll
    for (int s = 0; s < 16; s++) {
        const double2 cv = *(const double2*)(C + (size_t)s * DMODEL + 4 * t);
        cd0[s] = cv.x;
        cd1[s] = cv.y;
    }
    const double2 dd = *(const double2*)(D + 4 * t);

#pragma unroll 4
    for (int r = 0; r < 32; r++) {
        const double2 xv = *(const double2*)(x + (size_t)(row0 + r) * DMODEL + 4 * t);
        double a0 = mul2(xv.x, dd.x);
        double a1 = mul2(xv.y, dd.y);
#pragma unroll
        for (int s = 0; s < 16; s++) {
            const double h2 = shh2[s][r];
            a0 = fma2(h2, cd0[s], a0);
            a1 = fma2(h2, cd1[s], a1);
        }
        double2 yv; yv.x = a0; yv.y = a1;
        *(double2*)(y + (size_t)(row0 + r) * DMODEL + 4 * t) = yv;
    }
}

extern "C" void kernel_launch(void* const* d_in, const int* in_sizes, int n_in,
                              void* d_out, int out_size) {
    const float* x    = (const float*)d_in[0];   // [4,4096,1024]
    const float* A    = (const float*)d_in[1];   // [1,16]
    const float* B_in = (const float*)d_in[2];   // [1024,16]
    const float* C    = (const float*)d_in[3];   // [16,1024]
    const float* D    = (const float*)d_in[4];   // [1024]
    float* y = (float*)d_out;                    // [4,4096,1024]

    bx_kernel<<<256, 256>>>(x, A, B_in);
    chunkscan_kernel<<<64, 128>>>();
    out_kernel<<<512, 256>>>(x, C, D, y);
}

// round 6
// speedup vs baseline: 1.9008x; 1.9008x over previous
#include <cuda_runtime.h>
#include <cstdint>

#define BATCH 4
#define SEQLEN 4096
#define DMODEL 1024
#define DSTATE 16
#define NROWS (BATCH*SEQLEN)
#define NCHUNK 128                // 32-row chunks per sequence

// Scratch in [b][s][n] layout
__device__ float g_bx[NROWS*DSTATE];
__device__ float g_decay[NROWS*DSTATE];
__device__ float g_cA[BATCH*DSTATE*NCHUNK];   // per-chunk decay product
__device__ float g_cH[BATCH*DSTATE*NCHUNK];   // per-chunk h (seed 0)

// ---- packed f32x2 helpers ---------------------------------------------------
__device__ __forceinline__ double pk2(float lo, float hi) {
    double d; asm("mov.b64 %0, {%1, %2};" : "=d"(d) : "f"(lo), "f"(hi)); return d;
}
__device__ __forceinline__ double fma2(double a, double b, double c) {
    double d; asm("fma.rn.f32x2 %0, %1, %2, %3;" : "=d"(d) : "d"(a), "d"(b), "d"(c)); return d;
}
__device__ __forceinline__ double mul2(double a, double b) {
    double d; asm("mul.rn.f32x2 %0, %1, %2;" : "=d"(d) : "d"(a), "d"(b)); return d;
}
__device__ __forceinline__ double add2(double a, double b) {
    double d; asm("add.rn.f32x2 %0, %1, %2;" : "=d"(d) : "d"(a), "d"(b)); return d;
}
__device__ __forceinline__ float lo2(double d) { return __int_as_float(__double2loint(d)); }
__device__ __forceinline__ float hi2(double d) { return __int_as_float(__double2hiint(d)); }

// ---------------------------------------------------------------------------
// Kernel 1: Bx = x @ B_in ; decay = exp(softplus(Bx) * -exp(A))
// 512 blocks x 32 rows, 128 threads. Thread (c=t&15, rgrp=t>>4) owns 4 rows,
// e-stripe e = c+16k. B staged at pitch 18 (18c mod 32 permutes 16 lanes ->
// conflict-free LDS.64; half-warp pairs broadcast). x prefetched one k ahead.
// Emits one per-chunk (32-row) affine summary per block.
// ---------------------------------------------------------------------------
__global__ __launch_bounds__(128, 5) void bx_kernel(const float* __restrict__ x,
                                                    const float* __restrict__ A,
                                                    const float* __restrict__ B_in) {
    __shared__ __align__(16) float sb[256 * 18];   // 18 KB B chunk
    __shared__ double sdump[32][8];                // 2 KB reduced sums
    __shared__ float sdec[DSTATE][33];
    __shared__ float sbxs[DSTATE][33];

    const int t = threadIdx.x;
    const int c = t & 15;
    const int rgrp = t >> 4;                       // 0..7
    const int row0 = blockIdx.x * 32 + rgrp * 4;

    double acc[4][8];
#pragma unroll
    for (int r = 0; r < 4; r++)
#pragma unroll
        for (int j = 0; j < 8; j++) acc[r][j] = 0.0;

    for (int ch = 0; ch < 4; ch++) {
        __syncthreads();
        // stage B[ch*256 .. +256) -> sb (pitch 18), coalesced
#pragma unroll
        for (int i = 0; i < 32; i++) {
            int idx = i * 128 + t;                 // 0..4095
            int e = idx >> 4, s = idx & 15;
            sb[e * 18 + s] = B_in[(size_t)ch * 4096 + idx];
        }
        __syncthreads();

        const float* xp = x + (size_t)row0 * DMODEL + ch * 256 + c;
        float nx[4];
#pragma unroll
        for (int r = 0; r < 4; r++) nx[r] = xp[r * DMODEL];

#pragma unroll
        for (int k = 0; k < 16; k++) {
            float cx[4];
#pragma unroll
            for (int r = 0; r < 4; r++) cx[r] = nx[r];
            if (k < 15) {
#pragma unroll
                for (int r = 0; r < 4; r++) nx[r] = xp[r * DMODEL + (k + 1) * 16];
            }
            double xx[4];
#pragma unroll
            for (int r = 0; r < 4; r++) xx[r] = pk2(cx[r], cx[r]);

            const double* bp = (const double*)(sb + (c + 16 * k) * 18);
            double bv[8];
#pragma unroll
            for (int j = 0; j < 8; j++) bv[j] = bp[j];
#pragma unroll
            for (int r = 0; r < 4; r++)
#pragma unroll
                for (int j = 0; j < 8; j++)
                    acc[r][j] = fma2(xx[r], bv[j], acc[r][j]);
        }
    }

    // reduce across the 16 c-lanes
#pragma unroll
    for (int off = 1; off < 16; off <<= 1) {
#pragma unroll
        for (int r = 0; r < 4; r++)
#pragma unroll
            for (int j = 0; j < 8; j++) {
                double o = __shfl_xor_sync(0xffffffffu, acc[r][j], off);
                acc[r][j] = add2(acc[r][j], o);
            }
    }

    __syncthreads();
    if (c == 0) {
#pragma unroll
        for (int r = 0; r < 4; r++)
#pragma unroll
            for (int j = 0; j < 8; j++) sdump[rgrp * 4 + r][j] = acc[r][j];
    }
    __syncthreads();

    // softplus/exp: 256 items (32 rows x 8 doubles), 2 per thread
#pragma unroll
    for (int i = 0; i < 2; i++) {
        const int idx = i * 128 + t;
        const int rl = idx >> 3, q = idx & 7;
        const double v = sdump[rl][q];
        const float bx0 = lo2(v), bx1 = hi2(v);
        const int s0 = 2 * q;
        const float an0 = -expf(A[s0]);
        const float an1 = -expf(A[s0 + 1]);
        const float sp0 = (bx0 > 20.f) ? bx0 : log1pf(expf(bx0));
        const float sp1 = (bx1 > 20.f) ? bx1 : log1pf(expf(bx1));
        sdec[s0][rl] = expf(sp0 * an0);
        sdec[s0 + 1][rl] = expf(sp1 * an1);
        sbxs[s0][rl] = bx0;
        sbxs[s0 + 1][rl] = bx1;
    }
    __syncthreads();

    const int b = blockIdx.x >> 7;                 // 128 blocks per batch
    const int n0 = (blockIdx.x * 32) & (SEQLEN - 1);
    // coalesced global writes of bx / decay in [b][s][n]
#pragma unroll
    for (int i = 0; i < 4; i++) {
        int idx = i * 128 + t;
        int s = idx >> 5, j = idx & 31;
        size_t o = ((size_t)(b * DSTATE + s)) * SEQLEN + n0 + j;
        g_bx[o] = sbxs[s][j];
        g_decay[o] = sdec[s][j];
    }
    // per-chunk summary: this block IS chunk (blockIdx & 127) for each s
    if (t < DSTATE) {
        float a = 1.f, h = 0.f;
#pragma unroll
        for (int j = 0; j < 32; j++) {
            const float d = sdec[t][j];
            h = fmaf(h, d, sbxs[t][j]);
            a *= d;
        }
        const int so = (b * DSTATE + t) * NCHUNK + (blockIdx.x & 127);
        g_cA[so] = a;
        g_cH[so] = h;
    }
}

// ---------------------------------------------------------------------------
// Kernel 2: per-block prefix (serial over <=127 L2-hot chunk summaries) +
// replay 32-row chunk + y = hs@C + x*D.
// 1024 blocks x (32 rows x 512 cols), 128 threads; thread owns 4 cols.
// h duplicated (h,h) in [r][s] order -> 8 broadcast LDS.128 + 32 FFMA2 / row.
// ---------------------------------------------------------------------------
__global__ __launch_bounds__(128, 5) void out_kernel(const float* __restrict__ x,
                                                     const float* __restrict__ C,
                                                     const float* __restrict__ D,
                                                     float* __restrict__ y) {
    __shared__ float sd[DSTATE][33], sv[DSTATE][33];
    __shared__ __align__(16) double hd[32][16];    // (h,h) pairs, [row][s]
    const int t = threadIdx.x;
    const int rb = blockIdx.x >> 1;
    const int half = blockIdx.x & 1;
    const int row0 = rb * 32;
    const int b = row0 >> 12, n0 = row0 & (SEQLEN - 1);
    const int chunk = rb & 127;
    const int c0 = half * 512 + 4 * t;

    // stage decay/bx tiles [16 s][32 n] (coalesced)
#pragma unroll
    for (int i = 0; i < 4; i++) {
        int idx = i * 128 + t;
        int s = idx >> 5, j = idx & 31;
        size_t o = ((size_t)(b * DSTATE + s)) * SEQLEN + n0 + j;
        sd[s][j] = g_decay[o];
        sv[s][j] = g_bx[o];
    }
    __syncthreads();

    // exclusive prefix for this chunk (serial, L2-hot) + replay
    if (t < DSTATE) {
        const float* pA = g_cA + (b * DSTATE + t) * NCHUNK;
        const float* pH = g_cH + (b * DSTATE + t) * NCHUNK;
        float h = 0.f;
        for (int j = 0; j < chunk; j++)
            h = fmaf(h, pA[j], pH[j]);
#pragma unroll
        for (int j = 0; j < 32; j++) {
            h = fmaf(h, sd[t][j], sv[t][j]);
            hd[j][t] = pk2(h, h);
        }
    }
    __syncthreads();

    // C columns [c0, c0+4) as natural packed doubles (pairs of floats)
    double cd0[16], cd1[16];
#pragma unroll
    for (int s = 0; s < 16; s++) {
        const double2 cv = *(const double2*)(C + (size_t)s * DMODEL + c0);
        cd0[s] = cv.x;
        cd1[s] = cv.y;
    }
    const double2 dd = *(const double2*)(D + c0);

    const float* xrow = x + (size_t)row0 * DMODEL + c0;
    float* yrow = y + (size_t)row0 * DMODEL + c0;
    double2 nx = *(const double2*)xrow;

#pragma unroll 4
    for (int r = 0; r < 32; r++) {
        const double2 cx = nx;
        if (r < 31) nx = *(const double2*)(xrow + (size_t)(r + 1) * DMODEL);
        double a0 = mul2(cx.x, dd.x);
        double a1 = mul2(cx.y, dd.y);
#pragma unroll
        for (int q = 0; q < 8; q++) {
            const double2 h2 = *(const double2*)&hd[r][2 * q];
            a0 = fma2(h2.x, cd0[2 * q], a0);
            a1 = fma2(h2.x, cd1[2 * q], a1);
            a0 = fma2(h2.y, cd0[2 * q + 1], a0);
            a1 = fma2(h2.y, cd1[2 * q + 1], a1);
        }
        double2 yv; yv.x = a0; yv.y = a1;
        *(double2*)(yrow + (size_t)r * DMODEL) = yv;
    }
}

extern "C" void kernel_launch(void* const* d_in, const int* in_sizes, int n_in,
                              void* d_out, int out_size) {
    const float* x    = (const float*)d_in[0];   // [4,4096,1024]
    const float* A    = (const float*)d_in[1];   // [1,16]
    const float* B_in = (const float*)d_in[2];   // [1024,16]
    const float* C    = (const float*)d_in[3];   // [16,1024]
    const float* D    = (const float*)d_in[4];   // [1024]
    float* y = (float*)d_out;                    // [4,4096,1024]

    bx_kernel<<<512, 128>>>(x, A, B_in);
    out_kernel<<<1024, 128>>>(x, C, D, y);
}

// round 7
// speedup vs baseline: 2.4518x; 1.2899x over previous
#include <cuda_runtime.h>
#include <cstdint>

#define BATCH 4
#define SEQLEN 4096
#define DMODEL 1024
#define DSTATE 16
#define NROWS (BATCH*SEQLEN)
#define NCHUNK 256                // 16-row chunks per sequence

// Scratch in [b][s][n] layout
__device__ float g_bx[NROWS*DSTATE];
__device__ float g_decay[NROWS*DSTATE];
__device__ float g_cA[BATCH*DSTATE*NCHUNK];
__device__ float g_cH[BATCH*DSTATE*NCHUNK];
__device__ float g_hpre[BATCH*DSTATE*NCHUNK];

// ---- packed f32x2 helpers ---------------------------------------------------
__device__ __forceinline__ double pk2(float lo, float hi) {
    double d; asm("mov.b64 %0, {%1, %2};" : "=d"(d) : "f"(lo), "f"(hi)); return d;
}
__device__ __forceinline__ double fma2(double a, double b, double c) {
    double d; asm("fma.rn.f32x2 %0, %1, %2, %3;" : "=d"(d) : "d"(a), "d"(b), "d"(c)); return d;
}
__device__ __forceinline__ double mul2(double a, double b) {
    double d; asm("mul.rn.f32x2 %0, %1, %2;" : "=d"(d) : "d"(a), "d"(b)); return d;
}
__device__ __forceinline__ double add2(double a, double b) {
    double d; asm("add.rn.f32x2 %0, %1, %2;" : "=d"(d) : "d"(a), "d"(b)); return d;
}
__device__ __forceinline__ float lo2(double d) { return __int_as_float(__double2loint(d)); }
__device__ __forceinline__ float hi2(double d) { return __int_as_float(__double2hiint(d)); }
__device__ __forceinline__ void stcs2(void* p, double a, double b) {
    asm volatile("st.global.cs.v2.f64 [%0], {%1, %2};" :: "l"(p), "d"(a), "d"(b) : "memory");
}

// ---------------------------------------------------------------------------
// Kernel 1: Bx = x @ B_in ; decay = exp(softplus(Bx) * -exp(A))
// 512 blocks x 32 rows, 128 threads; thread (c=t&15, rgrp=t>>4) owns 4 rows.
// B staged in 512-row stages (36 KB, pitch 18 -> conflict-free LDS.64).
// 2-deep x prefetch (8 outstanding LDG per thread) to cover DRAM latency
// at the grid-limited ~14 warps/SM. Emits two 16-row chunk summaries.
// ---------------------------------------------------------------------------
__global__ __launch_bounds__(128, 4) void bx_kernel(const float* __restrict__ x,
                                                    const float* __restrict__ A,
                                                    const float* __restrict__ B_in) {
    __shared__ __align__(16) float sb[512 * 18];   // 36 KB
    __shared__ double sdump[32][8];
    __shared__ float sdec[DSTATE][33];
    __shared__ float sbxs[DSTATE][33];

    const int t = threadIdx.x;
    const int c = t & 15;
    const int rgrp = t >> 4;
    const int row0 = blockIdx.x * 32 + rgrp * 4;

    double acc[4][8];
#pragma unroll
    for (int r = 0; r < 4; r++)
#pragma unroll
        for (int j = 0; j < 8; j++) acc[r][j] = 0.0;

    for (int stage = 0; stage < 2; stage++) {
        __syncthreads();
        // stage B rows [stage*512, +512) -> sb pitch 18 (float4 gmem, 2x STS.64)
        const float4* bsrc = (const float4*)(B_in + (size_t)stage * 512 * DSTATE);
#pragma unroll
        for (int i = 0; i < 16; i++) {
            int idx = i * 128 + t;                 // float4 unit 0..2047
            int e = idx >> 2, u = idx & 3;
            float4 v = bsrc[idx];
            double* dst = (double*)(sb + e * 18 + u * 4);
            dst[0] = ((const double*)&v)[0];
            dst[1] = ((const double*)&v)[1];
        }
        __syncthreads();

        const float* xp = x + (size_t)row0 * DMODEL + stage * 512 + c;
        float p0[4], p1[4];
#pragma unroll
        for (int r = 0; r < 4; r++) {
            p0[r] = xp[r * DMODEL];
            p1[r] = xp[r * DMODEL + 16];
        }

#pragma unroll 16
        for (int k = 0; k < 32; k++) {
            float cx[4];
#pragma unroll
            for (int r = 0; r < 4; r++) { cx[r] = p0[r]; p0[r] = p1[r]; }
            if (k < 30) {
#pragma unroll
                for (int r = 0; r < 4; r++) p1[r] = xp[r * DMODEL + (k + 2) * 16];
            }
            double xx[4];
#pragma unroll
            for (int r = 0; r < 4; r++) xx[r] = pk2(cx[r], cx[r]);

            const double* bp = (const double*)(sb + (c + 16 * k) * 18);
            double bv[8];
#pragma unroll
            for (int j = 0; j < 8; j++) bv[j] = bp[j];
#pragma unroll
            for (int r = 0; r < 4; r++)
#pragma unroll
                for (int j = 0; j < 8; j++)
                    acc[r][j] = fma2(xx[r], bv[j], acc[r][j]);
        }
    }

    // reduce across the 16 c-lanes
#pragma unroll
    for (int off = 1; off < 16; off <<= 1) {
#pragma unroll
        for (int r = 0; r < 4; r++)
#pragma unroll
            for (int j = 0; j < 8; j++) {
                double o = __shfl_xor_sync(0xffffffffu, acc[r][j], off);
                acc[r][j] = add2(acc[r][j], o);
            }
    }

    __syncthreads();
    if (c == 0) {
#pragma unroll
        for (int r = 0; r < 4; r++)
#pragma unroll
            for (int j = 0; j < 8; j++) sdump[rgrp * 4 + r][j] = acc[r][j];
    }
    __syncthreads();

    // softplus/exp: 256 items, 2 per thread
#pragma unroll
    for (int i = 0; i < 2; i++) {
        const int idx = i * 128 + t;
        const int rl = idx >> 3, q = idx & 7;
        const double v = sdump[rl][q];
        const float bx0 = lo2(v), bx1 = hi2(v);
        const int s0 = 2 * q;
        const float an0 = -expf(A[s0]);
        const float an1 = -expf(A[s0 + 1]);
        const float sp0 = (bx0 > 20.f) ? bx0 : log1pf(expf(bx0));
        const float sp1 = (bx1 > 20.f) ? bx1 : log1pf(expf(bx1));
        sdec[s0][rl] = expf(sp0 * an0);
        sdec[s0 + 1][rl] = expf(sp1 * an1);
        sbxs[s0][rl] = bx0;
        sbxs[s0 + 1][rl] = bx1;
    }
    __syncthreads();

    const int b = blockIdx.x >> 7;
    const int n0 = (blockIdx.x * 32) & (SEQLEN - 1);
#pragma unroll
    for (int i = 0; i < 4; i++) {
        int idx = i * 128 + t;
        int s = idx >> 5, j = idx & 31;
        size_t o = ((size_t)(b * DSTATE + s)) * SEQLEN + n0 + j;
        g_bx[o] = sbxs[s][j];
        g_decay[o] = sdec[s][j];
    }
    // two 16-row chunk summaries per block
    if (t < 32) {
        const int s = t & 15, half = t >> 4;
        float a = 1.f, h = 0.f;
#pragma unroll
        for (int j = 0; j < 16; j++) {
            const int jj = half * 16 + j;
            const float d = sdec[s][jj];
            h = fmaf(h, d, sbxs[s][jj]);
            a *= d;
        }
        const int so = (b * DSTATE + s) * NCHUNK + (blockIdx.x & 127) * 2 + half;
        g_cA[so] = a;
        g_cH[so] = h;
    }
}

// ---------------------------------------------------------------------------
// Kernel 2: scan 256 chunk summaries per (b,s); write EXCLUSIVE prefix.
// ---------------------------------------------------------------------------
__global__ __launch_bounds__(256) void chunkscan_kernel() {
    __shared__ float sA[256], sH[256];
    const int t = threadIdx.x;
    const int seq = blockIdx.x;                    // b*16 + s
    float a = g_cA[seq * NCHUNK + t];
    float h = g_cH[seq * NCHUNK + t];
    sA[t] = a; sH[t] = h;
    __syncthreads();
#pragma unroll
    for (int off = 1; off < 256; off <<= 1) {
        float pa = 1.f, ph = 0.f;
        const bool act = (t >= off);
        if (act) { pa = sA[t - off]; ph = sH[t - off]; }
        __syncthreads();
        if (act) {
            h = fmaf(a, ph, h);
            a = a * pa;
            sA[t] = a; sH[t] = h;
        }
        __syncthreads();
    }
    g_hpre[seq * NCHUNK + t] = (t == 0) ? 0.f : sH[t - 1];
}

// ---------------------------------------------------------------------------
// Kernel 3: replay 16-row chunk from precomputed prefix + y = hs@C + x*D.
// 2048 blocks x (16 rows x 512 cols), 128 threads; thread owns 4 cols.
// 4-deep x prefetch; y stored with st.global.cs (evict-first).
// ---------------------------------------------------------------------------
__global__ __launch_bounds__(128, 4) void out_kernel(const float* __restrict__ x,
                                                     const float* __restrict__ C,
                                                     const float* __restrict__ D,
                                                     float* __restrict__ y) {
    __shared__ float sd[DSTATE][17], sv[DSTATE][17];
    __shared__ __align__(16) double hd[16][16];    // (h,h) pairs, [row][s]
    const int t = threadIdx.x;
    const int rb = blockIdx.x >> 1;
    const int half = blockIdx.x & 1;
    const int row0 = rb * 16;
    const int b = rb >> 8, n0 = row0 & (SEQLEN - 1);
    const int chunk = rb & 255;
    const int c0 = half * 512 + 4 * t;

    // stage decay/bx tiles [16 s][16 n] (2 elems/thread)
#pragma unroll
    for (int i = 0; i < 2; i++) {
        int idx = i * 128 + t;
        int s = idx >> 4, j = idx & 15;
        size_t o = ((size_t)(b * DSTATE + s)) * SEQLEN + n0 + j;
        sd[s][j] = g_decay[o];
        sv[s][j] = g_bx[o];
    }
    __syncthreads();

    // replay this 16-row chunk from the precomputed exclusive prefix
    if (t < DSTATE) {
        float h = g_hpre[(b * DSTATE + t) * NCHUNK + chunk];
#pragma unroll
        for (int j = 0; j < 16; j++) {
            h = fmaf(h, sd[t][j], sv[t][j]);
            hd[j][t] = pk2(h, h);
        }
    }
    __syncthreads();

    // C columns [c0, c0+4) as natural packed doubles
    double cd0[16], cd1[16];
#pragma unroll
    for (int s = 0; s < 16; s++) {
        const double2 cv = *(const double2*)(C + (size_t)s * DMODEL + c0);
        cd0[s] = cv.x;
        cd1[s] = cv.y;
    }
    const double2 dd = *(const double2*)(D + c0);

    const float* xrow = x + (size_t)row0 * DMODEL + c0;
    float* yrow = y + (size_t)row0 * DMODEL + c0;

    double2 nx[4];
#pragma unroll
    for (int i = 0; i < 4; i++)
        nx[i] = *(const double2*)(xrow + (size_t)i * DMODEL);

#pragma unroll
    for (int r = 0; r < 16; r++) {
        const double2 cx = nx[r & 3];
        if (r + 4 < 16)
            nx[r & 3] = *(const double2*)(xrow + (size_t)(r + 4) * DMODEL);
        double a0 = mul2(cx.x, dd.x);
        double a1 = mul2(cx.y, dd.y);
#pragma unroll
        for (int q = 0; q < 8; q++) {
            const double2 h2 = *(const double2*)&hd[r][2 * q];
            a0 = fma2(h2.x, cd0[2 * q], a0);
            a1 = fma2(h2.x, cd1[2 * q], a1);
            a0 = fma2(h2.y, cd0[2 * q + 1], a0);
            a1 = fma2(h2.y, cd1[2 * q + 1], a1);
        }
        stcs2(yrow + (size_t)r * DMODEL, a0, a1);
    }
}

extern "C" void kernel_launch(void* const* d_in, const int* in_sizes, int n_in,
                              void* d_out, int out_size) {
    const float* x    = (const float*)d_in[0];   // [4,4096,1024]
    const float* A    = (const float*)d_in[1];   // [1,16]
    const float* B_in = (const float*)d_in[2];   // [1024,16]
    const float* C    = (const float*)d_in[3];   // [16,1024]
    const float* D    = (const float*)d_in[4];   // [1024]
    float* y = (float*)d_out;                    // [4,4096,1024]

    bx_kernel<<<512, 128>>>(x, A, B_in);
    chunkscan_kernel<<<64, 256>>>();
    out_kernel<<<2048, 128>>>(x, C, D, y);
}

// round 8
// speedup vs baseline: 2.4843x; 1.0133x over previous
#include <cuda_runtime.h>
#include <cstdint>

#define BATCH 4
#define SEQLEN 4096
#define DMODEL 1024
#define DSTATE 16
#define NROWS (BATCH*SEQLEN)
#define NCHUNK 256                // 16-row chunks per sequence

// Scratch
__device__ double g_partd[2*NROWS*8];          // packed f32x2 partial sums, per e-half
__device__ float g_bx[NROWS*DSTATE];           // [b][s][n]
__device__ float g_decay[NROWS*DSTATE];        // [b][s][n]
__device__ float g_cA[BATCH*DSTATE*NCHUNK];
__device__ float g_cH[BATCH*DSTATE*NCHUNK];
__device__ float g_hpre[BATCH*DSTATE*NCHUNK];

// ---- packed f32x2 helpers ---------------------------------------------------
__device__ __forceinline__ double pk2(float lo, float hi) {
    double d; asm("mov.b64 %0, {%1, %2};" : "=d"(d) : "f"(lo), "f"(hi)); return d;
}
__device__ __forceinline__ double fma2(double a, double b, double c) {
    double d; asm("fma.rn.f32x2 %0, %1, %2, %3;" : "=d"(d) : "d"(a), "d"(b), "d"(c)); return d;
}
__device__ __forceinline__ double mul2(double a, double b) {
    double d; asm("mul.rn.f32x2 %0, %1, %2;" : "=d"(d) : "d"(a), "d"(b)); return d;
}
__device__ __forceinline__ double add2(double a, double b) {
    double d; asm("add.rn.f32x2 %0, %1, %2;" : "=d"(d) : "d"(a), "d"(b)); return d;
}
__device__ __forceinline__ float lo2(double d) { return __int_as_float(__double2loint(d)); }
__device__ __forceinline__ float hi2(double d) { return __int_as_float(__double2hiint(d)); }
__device__ __forceinline__ void stcs2(void* p, double a, double b) {
    asm volatile("st.global.cs.v2.f64 [%0], {%1, %2};" :: "l"(p), "d"(a), "d"(b) : "memory");
}

// ---------------------------------------------------------------------------
// Kernel 1: partial Bx over one e-half.
// Grid 1024: block (rb = bid>>1) rows rb*32..+32, (q = bid&1) e in [q*512,+512).
// 128 threads; thread (c=t&15, rgrp=t>>4) owns 4 rows, e = q*512 + c + 16k.
// B half staged at pitch 18 (conflict-free LDS.64). 2-deep x prefetch.
// Writes 32x8 packed partial sums to g_partd.
// ---------------------------------------------------------------------------
__global__ __launch_bounds__(128, 4) void bx_kernel(const float* __restrict__ x,
                                                    const float* __restrict__ B_in) {
    __shared__ __align__(16) float sb[512 * 18];   // 36 KB
    __shared__ double sdump[32][8];

    const int t = threadIdx.x;
    const int c = t & 15;
    const int rgrp = t >> 4;
    const int rb = blockIdx.x >> 1;
    const int q = blockIdx.x & 1;
    const int row0 = rb * 32 + rgrp * 4;

    // stage B rows [q*512, +512) -> sb pitch 18
    const float4* bsrc = (const float4*)(B_in + (size_t)q * 512 * DSTATE);
#pragma unroll
    for (int i = 0; i < 16; i++) {
        int idx = i * 128 + t;                     // float4 unit 0..2047
        int e = idx >> 2, u = idx & 3;
        float4 v = bsrc[idx];
        double* dst = (double*)(sb + e * 18 + u * 4);
        dst[0] = ((const double*)&v)[0];
        dst[1] = ((const double*)&v)[1];
    }

    double acc[4][8];
#pragma unroll
    for (int r = 0; r < 4; r++)
#pragma unroll
        for (int j = 0; j < 8; j++) acc[r][j] = 0.0;

    const float* xp = x + (size_t)row0 * DMODEL + q * 512 + c;
    float p0[4], p1[4];
#pragma unroll
    for (int r = 0; r < 4; r++) {
        p0[r] = xp[r * DMODEL];
        p1[r] = xp[r * DMODEL + 16];
    }
    __syncthreads();

#pragma unroll 16
    for (int k = 0; k < 32; k++) {
        float cx[4];
#pragma unroll
        for (int r = 0; r < 4; r++) { cx[r] = p0[r]; p0[r] = p1[r]; }
        if (k < 30) {
#pragma unroll
            for (int r = 0; r < 4; r++) p1[r] = xp[r * DMODEL + (k + 2) * 16];
        }
        double xx[4];
#pragma unroll
        for (int r = 0; r < 4; r++) xx[r] = pk2(cx[r], cx[r]);

        const double* bp = (const double*)(sb + (c + 16 * k) * 18);
        double bv[8];
#pragma unroll
        for (int j = 0; j < 8; j++) bv[j] = bp[j];
#pragma unroll
        for (int r = 0; r < 4; r++)
#pragma unroll
            for (int j = 0; j < 8; j++)
                acc[r][j] = fma2(xx[r], bv[j], acc[r][j]);
    }

    // reduce across the 16 c-lanes
#pragma unroll
    for (int off = 1; off < 16; off <<= 1) {
#pragma unroll
        for (int r = 0; r < 4; r++)
#pragma unroll
            for (int j = 0; j < 8; j++) {
                double o = __shfl_xor_sync(0xffffffffu, acc[r][j], off);
                acc[r][j] = add2(acc[r][j], o);
            }
    }

    __syncthreads();
    if (c == 0) {
#pragma unroll
        for (int r = 0; r < 4; r++)
#pragma unroll
            for (int j = 0; j < 8; j++) sdump[rgrp * 4 + r][j] = acc[r][j];
    }
    __syncthreads();

    // coalesced partial write: 256 doubles
    double* gp = g_partd + ((size_t)q * NROWS + rb * 32) * 8;
#pragma unroll
    for (int i = 0; i < 2; i++) {
        int idx = i * 128 + t;
        gp[idx] = sdump[idx >> 3][idx & 7];
    }
}

// ---------------------------------------------------------------------------
// Kernel 2: combine e-halves + softplus/exp + transpose to [b][s][n] +
// 16-row chunk summaries. Grid 256 x 128 threads, 64 rows per block.
// ---------------------------------------------------------------------------
__global__ __launch_bounds__(128) void combine_kernel(const float* __restrict__ A) {
    __shared__ float sdec[DSTATE][65];
    __shared__ float sbxs[DSTATE][65];
    const int t = threadIdx.x;
    const int row0 = blockIdx.x * 64;

    const double* p0 = g_partd + (size_t)row0 * 8;
    const double* p1 = g_partd + ((size_t)NROWS + row0) * 8;
#pragma unroll
    for (int i = 0; i < 4; i++) {
        const int idx = i * 128 + t;               // 0..511 (64 rows x 8 pairs)
        const int rl = idx >> 3, qq = idx & 7;
        const double v = add2(p0[idx], p1[idx]);
        const float bx0 = lo2(v), bx1 = hi2(v);
        const int s0 = 2 * qq;
        const float an0 = -expf(A[s0]);
        const float an1 = -expf(A[s0 + 1]);
        const float sp0 = (bx0 > 20.f) ? bx0 : log1pf(expf(bx0));
        const float sp1 = (bx1 > 20.f) ? bx1 : log1pf(expf(bx1));
        sdec[s0][rl] = expf(sp0 * an0);
        sdec[s0 + 1][rl] = expf(sp1 * an1);
        sbxs[s0][rl] = bx0;
        sbxs[s0 + 1][rl] = bx1;
    }
    __syncthreads();

    const int b = row0 >> 12;
    const int n0 = row0 & (SEQLEN - 1);
    // coalesced writes in [b][s][n]
#pragma unroll
    for (int i = 0; i < 8; i++) {
        int idx = i * 128 + t;                     // 0..1023 (16 s x 64 n)
        int s = idx >> 6, j = idx & 63;
        size_t o = ((size_t)(b * DSTATE + s)) * SEQLEN + n0 + j;
        g_bx[o] = sbxs[s][j];
        g_decay[o] = sdec[s][j];
    }
    // four 16-row chunk summaries
    if (t < 64) {
        const int s = t & 15, ci = t >> 4;
        float a = 1.f, h = 0.f;
#pragma unroll
        for (int j = 0; j < 16; j++) {
            const int jj = ci * 16 + j;
            const float d = sdec[s][jj];
            h = fmaf(h, d, sbxs[s][jj]);
            a *= d;
        }
        const int so = (b * DSTATE + s) * NCHUNK + (n0 >> 4) + ci;
        g_cA[so] = a;
        g_cH[so] = h;
    }
}

// ---------------------------------------------------------------------------
// Kernel 3: scan 256 chunk summaries per (b,s); write EXCLUSIVE prefix.
// ---------------------------------------------------------------------------
__global__ __launch_bounds__(256) void chunkscan_kernel() {
    __shared__ float sA[256], sH[256];
    const int t = threadIdx.x;
    const int seq = blockIdx.x;                    // b*16 + s
    float a = g_cA[seq * NCHUNK + t];
    float h = g_cH[seq * NCHUNK + t];
    sA[t] = a; sH[t] = h;
    __syncthreads();
#pragma unroll
    for (int off = 1; off < 256; off <<= 1) {
        float pa = 1.f, ph = 0.f;
        const bool act = (t >= off);
        if (act) { pa = sA[t - off]; ph = sH[t - off]; }
        __syncthreads();
        if (act) {
            h = fmaf(a, ph, h);
            a = a * pa;
            sA[t] = a; sH[t] = h;
        }
        __syncthreads();
    }
    g_hpre[seq * NCHUNK + t] = (t == 0) ? 0.f : sH[t - 1];
}

// ---------------------------------------------------------------------------
// Kernel 4: replay 16-row chunk + y = hs@C + x*D.
// 2048 blocks x (16 rows x 512 cols), 128 threads; thread owns 4 cols.
// x is loaded ONLY if this thread's D slice is nonzero (generally correct;
// with D == 0 the entire x read disappears). y stored evict-first.
// ---------------------------------------------------------------------------
__global__ __launch_bounds__(128, 4) void out_kernel(const float* __restrict__ x,
                                                     const float* __restrict__ C,
                                                     const float* __restrict__ D,
                                                     float* __restrict__ y) {
    __shared__ float sd[DSTATE][17], sv[DSTATE][17];
    __shared__ __align__(16) double hd[16][16];    // (h,h) pairs, [row][s]
    const int t = threadIdx.x;
    const int rb = blockIdx.x >> 1;
    const int half = blockIdx.x & 1;
    const int row0 = rb * 16;
    const int b = rb >> 8, n0 = row0 & (SEQLEN - 1);
    const int chunk = rb & 255;
    const int c0 = half * 512 + 4 * t;

    // stage decay/bx tiles [16 s][16 n]
#pragma unroll
    for (int i = 0; i < 2; i++) {
        int idx = i * 128 + t;
        int s = idx >> 4, j = idx & 15;
        size_t o = ((size_t)(b * DSTATE + s)) * SEQLEN + n0 + j;
        sd[s][j] = g_decay[o];
        sv[s][j] = g_bx[o];
    }
    __syncthreads();

    // replay this 16-row chunk from the precomputed exclusive prefix
    if (t < DSTATE) {
        float h = g_hpre[(b * DSTATE + t) * NCHUNK + chunk];
#pragma unroll
        for (int j = 0; j < 16; j++) {
            h = fmaf(h, sd[t][j], sv[t][j]);
            hd[j][t] = pk2(h, h);
        }
    }
    __syncthreads();

    // C columns [c0, c0+4) as natural packed doubles
    double cd0[16], cd1[16];
#pragma unroll
    for (int s = 0; s < 16; s++) {
        const double2 cv = *(const double2*)(C + (size_t)s * DMODEL + c0);
        cd0[s] = cv.x;
        cd1[s] = cv.y;
    }
    const float4 dv = *(const float4*)(D + c0);
    const bool needx = (dv.x != 0.f) || (dv.y != 0.f) || (dv.z != 0.f) || (dv.w != 0.f);
    const double dd0 = pk2(dv.x, dv.y), dd1 = pk2(dv.z, dv.w);

    const float* xrow = x + (size_t)row0 * DMODEL + c0;
    float* yrow = y + (size_t)row0 * DMODEL + c0;

    double2 nx[4];
    if (needx) {
#pragma unroll
        for (int i = 0; i < 4; i++)
            nx[i] = *(const double2*)(xrow + (size_t)i * DMODEL);
    }

#pragma unroll
    for (int r = 0; r < 16; r++) {
        double a0, a1;
        if (needx) {
            const double2 cx = nx[r & 3];
            if (r + 4 < 16)
                nx[r & 3] = *(const double2*)(xrow + (size_t)(r + 4) * DMODEL);
            a0 = mul2(cx.x, dd0);
            a1 = mul2(cx.y, dd1);
        } else {
            a0 = 0.0; a1 = 0.0;
        }
#pragma unroll
        for (int qq = 0; qq < 8; qq++) {
            const double2 h2 = *(const double2*)&hd[r][2 * qq];
            a0 = fma2(h2.x, cd0[2 * qq], a0);
            a1 = fma2(h2.x, cd1[2 * qq], a1);
            a0 = fma2(h2.y, cd0[2 * qq + 1], a0);
            a1 = fma2(h2.y, cd1[2 * qq + 1], a1);
        }
        stcs2(yrow + (size_t)r * DMODEL, a0, a1);
    }
}

extern "C" void kernel_launch(void* const* d_in, const int* in_sizes, int n_in,
                              void* d_out, int out_size) {
    const float* x    = (const float*)d_in[0];   // [4,4096,1024]
    const float* A    = (const float*)d_in[1];   // [1,16]
    const float* B_in = (const float*)d_in[2];   // [1024,16]
    const float* C    = (const float*)d_in[3];   // [16,1024]
    const float* D    = (const float*)d_in[4];   // [1024]
    float* y = (float*)d_out;                    // [4,4096,1024]

    bx_kernel<<<1024, 128>>>(x, B_in);
    combine_kernel<<<256, 128>>>(A);
    chunkscan_kernel<<<64, 256>>>();
    out_kernel<<<2048, 128>>>(x, C, D, y);
}